// round 17
// baseline (speedup 1.0000x reference)
#include <cuda_runtime.h>
#include <cuda_bf16.h>
#include <math.h>
#include <stdint.h>

#define NN 50000
#define EE 800000
#define DD 200
#define KP 208            // padded K / padded N for weights
#define BM 64             // M tile per CTA (occupancy-2, R14/R15-proven)
#define NTILES ((NN + BM - 1) / BM)   // 782

// smem stage layout (bytes); K-chunk = 32 cols, row stride 80B
#define SO_AHI 0
#define SO_ALO 5120
#define SO_BHI 10240
#define SO_BLO 26880
#define STAGE_BYTES 43520
#define SM_TOT (2 * STAGE_BYTES)      // 87040 per CTA; 2 CTAs/SM

// mega_prep role block counts (256 threads/block)
#define CNB   ((NN * 52 + 255) / 256)   // 10157 conv_node
#define CWB   ((KP * KP + 255) / 256)   // 169 conv_weight
#define BMTB  (13 * 13)                 // 169 bmt tiles
#define DEGB  ((EE + 255) / 256)        // 3125 deg
#define PKB   ((EE + 255) / 256)        // 3125 pack
#define MEGA_GRID (2 * CNB + 3 * CWB + BMTB + 1 + DEGB + PKB)

// edge grids
#define EB    ((EE * 50) / 256)         // 156250 (exact)
#define NRMB  ((NN + 255) / 256)        // 196 (norm tail on edge1)

// ================= device scratch =================
__device__ __align__(128) float g_agg[NN * DD];    // layer-1 aggregation
__device__ __align__(128) float g_agg2[NN * DD];   // layer-2 aggregation (double buffer)
__device__ __align__(128) float g_h1[NN * DD];
__device__ __align__(128) float g_norm[NN];        // deg counts -> 1/deg
__device__ __align__(128) float g_bfin[DD];
__device__ __align__(128) unsigned long long g_epk[EE];  // (et<<32)|(dst<<16)|src
__device__ __align__(128) __nv_bfloat16 g_xhi[NN * KP],  g_xlo[NN * KP];
__device__ __align__(128) __nv_bfloat16 g_h1hi[NN * KP], g_h1lo[NN * KP];
__device__ __align__(128) __nv_bfloat16 g_a2hi[NN * KP], g_a2lo[NN * KP];
__device__ __align__(128) __nv_bfloat16 g_h0hi[NN * KP], g_h0lo[NN * KP];
__device__ __align__(128) __nv_bfloat16 g_w1hi[KP * KP],  g_w1lo[KP * KP];
__device__ __align__(128) __nv_bfloat16 g_wihhi[KP * KP], g_wihlo[KP * KP];
__device__ __align__(128) __nv_bfloat16 g_whhhi[KP * KP], g_whhlo[KP * KP];
__device__ __align__(128) __nv_bfloat16 g_mthi[KP * KP],  g_mtlo[KP * KP];

// ================= role bodies =================
__device__ __forceinline__ void conv_node_body(int idx, const float* __restrict__ src,
                                               __nv_bfloat16* __restrict__ hi,
                                               __nv_bfloat16* __restrict__ lo,
                                               bool useNorm) {
    if (idx >= NN * 52) return;
    int n = idx / 52;
    int c4 = idx - n * 52;
    float4 v = make_float4(0.f, 0.f, 0.f, 0.f);
    if (c4 < 50) {
        v = *(const float4*)(src + (long)n * DD + c4 * 4);
        if (useNorm) {
            float nv = g_norm[n];
            v.x *= nv; v.y *= nv; v.z *= nv; v.w *= nv;
        }
    }
    __nv_bfloat16 h0 = __float2bfloat16(v.x);
    __nv_bfloat16 h1 = __float2bfloat16(v.y);
    __nv_bfloat16 h2 = __float2bfloat16(v.z);
    __nv_bfloat16 h3 = __float2bfloat16(v.w);
    __nv_bfloat162 hp0; hp0.x = h0; hp0.y = h1;
    __nv_bfloat162 hp1; hp1.x = h2; hp1.y = h3;
    __nv_bfloat162 lp0;
    lp0.x = __float2bfloat16(v.x - __bfloat162float(h0));
    lp0.y = __float2bfloat16(v.y - __bfloat162float(h1));
    __nv_bfloat162 lp1;
    lp1.x = __float2bfloat16(v.z - __bfloat162float(h2));
    lp1.y = __float2bfloat16(v.w - __bfloat162float(h3));
    long o = (long)n * KP + c4 * 4;
    *(__nv_bfloat162*)(hi + o) = hp0;
    *(__nv_bfloat162*)(hi + o + 2) = hp1;
    *(__nv_bfloat162*)(lo + o) = lp0;
    *(__nv_bfloat162*)(lo + o + 2) = lp1;
}

__device__ __forceinline__ void conv_weight_body(int idx, const float* __restrict__ src,
                                                 __nv_bfloat16* __restrict__ hi,
                                                 __nv_bfloat16* __restrict__ lo,
                                                 bool transpose) {
    if (idx >= KP * KP) return;
    int j = idx / KP;
    int c = idx - j * KP;
    float v = 0.0f;
    if (j < DD && c < DD) v = transpose ? src[c * DD + j] : src[j * DD + c];
    __nv_bfloat16 h = __float2bfloat16(v);
    hi[idx] = h;
    lo[idx] = __float2bfloat16(v - __bfloat162float(h));
}

// ================= mega_prep (R15/R16-proven; padzero role dropped —
// h1hi/h1lo conversion now writes pads itself) =================
__global__ __launch_bounds__(256) void mega_prep(
    const float* __restrict__ x, const float* __restrict__ dyn,
    const int* __restrict__ src, const int* __restrict__ dst,
    const int* __restrict__ et,
    const float* __restrict__ lw1, const float* __restrict__ Wih,
    const float* __restrict__ Whh, const float* __restrict__ lw2,
    const float* __restrict__ b2, const float* __restrict__ bih,
    const float* __restrict__ bhh) {
    __shared__ float sh[544];
    int b = blockIdx.x;
    int tid = threadIdx.x;

    if (b < CNB) {
        conv_node_body(b * 256 + tid, x, g_xhi, g_xlo, false);
        return;
    }
    b -= CNB;
    if (b < CNB) {
        conv_node_body(b * 256 + tid, dyn, g_h0hi, g_h0lo, false);
        return;
    }
    b -= CNB;
    if (b < CWB) {
        conv_weight_body(b * 256 + tid, lw1, g_w1hi, g_w1lo, true);
        return;
    }
    b -= CWB;
    if (b < CWB) {
        conv_weight_body(b * 256 + tid, Wih, g_wihhi, g_wihlo, false);
        return;
    }
    b -= CWB;
    if (b < CWB) {
        conv_weight_body(b * 256 + tid, Whh, g_whhhi, g_whhlo, false);
        return;
    }
    b -= CWB;
    if (b < BMTB) {                      // Mt[j][t] = sum_u Wih[j,u]*lw2[t,u]
        int tj = (b / 13) * 16;
        int tt = (b % 13) * 16;
        float* Ws = sh;
        float* Ls = sh + 272;
        int r = tid >> 4, cth = tid & 15;
        float s = 0.0f;
        for (int kb = 0; kb < DD; kb += 16) {
            int gk = kb + cth;
            int gj = tj + r, gt = tt + r;
            Ws[r * 17 + cth] = (gj < DD && gk < DD) ? Wih[gj * DD + gk] : 0.0f;
            Ls[r * 17 + cth] = (gt < DD && gk < DD) ? lw2[gt * DD + gk] : 0.0f;
            __syncthreads();
#pragma unroll
            for (int u = 0; u < 16; u++) s += Ws[r * 17 + u] * Ls[cth * 17 + u];
            __syncthreads();
        }
        int gj = tj + r, gt = tt + cth;
        if (gj < KP && gt < KP) {
            __nv_bfloat16 h = __float2bfloat16(s);
            g_mthi[gj * KP + gt] = h;
            g_mtlo[gj * KP + gt] = __float2bfloat16(s - __bfloat162float(h));
        }
        return;
    }
    b -= BMTB;
    if (b == 0) {                        // bfin
        for (int i = tid; i < DD; i += 256) sh[i] = b2[i];
        __syncthreads();
        if (tid < DD) {
            float s = bih[tid] + bhh[tid];
#pragma unroll 4
            for (int t = 0; t < DD; t++) s += sh[t] * Wih[tid * DD + t];
            g_bfin[tid] = s;
        }
        return;
    }
    b -= 1;
    if (b < DEGB) {                      // degree histogram
        int e = b * 256 + tid;
        if (e < EE) atomicAdd(&g_norm[dst[e]], 1.0f);
        return;
    }
    b -= DEGB;
    {                                    // pack edge indices
        int e = b * 256 + tid;
        if (e < EE)
            g_epk[e] = ((unsigned long long)(unsigned)et[e] << 32) |
                       ((unsigned long long)(unsigned)dst[e] << 16) |
                       (unsigned long long)(unsigned)src[e];
    }
}

// ================= edge message + scatter =================
__device__ __forceinline__ void edge_body(int idx, const float* __restrict__ x,
                                          const float* __restrict__ w,
                                          float* __restrict__ agg) {
    int e  = idx / 50;
    int b2 = idx - e * 50;

    unsigned long long pk = __ldg(&g_epk[e]);
    int s = (int)(pk & 0xffff);
    int d = (int)((pk >> 16) & 0xffff);
    int r = (int)(pk >> 32);

    float4 xv = *(const float4*)(x + (long)s * DD + b2 * 4);
    const float4* wp = (const float4*)(w + (long)r * 400 + b2 * 8);
    float4 wA = wp[0];
    float4 wB = wp[1];

    float o0 = xv.x * wA.x + xv.y * wA.z;
    float o1 = xv.x * wA.y + xv.y * wA.w;
    float o2 = xv.z * wB.x + xv.w * wB.z;
    float o3 = xv.z * wB.y + xv.w * wB.w;

    float* ap = agg + (long)d * DD + b2 * 4;
    asm volatile("red.global.add.v4.f32 [%0], {%1, %2, %3, %4};"
                 :: "l"(ap), "f"(o0), "f"(o1), "f"(o2), "f"(o3) : "memory");
}

// layer 1: edge role + norm-invert tail role
__global__ void edge1_kernel(const float* __restrict__ x,
                             const float* __restrict__ w) {
    int b = blockIdx.x;
    if (b < EB) {
        edge_body(b * 256 + threadIdx.x, x, w, g_agg);
    } else {
        int n = (b - EB) * 256 + threadIdx.x;
        if (n < NN) {
            float d = g_norm[n];
            g_norm[n] = (d > 0.0f) ? (1.0f / d) : 0.0f;
        }
    }
}

// layer 2: edge role (writes g_agg2) + h1->bf16 conversion tail role
// (conversion reads g_h1 — the SAME array the edge role gathers from,
//  so no new read working set; writes stream out under edge DRAM headroom)
__global__ void edge2_kernel(const float* __restrict__ x,
                             const float* __restrict__ w) {
    int b = blockIdx.x;
    if (b < EB) {
        edge_body(b * 256 + threadIdx.x, x, w, g_agg2);
    } else {
        conv_node_body((b - EB) * 256 + threadIdx.x, g_h1, g_h1hi, g_h1lo, false);
    }
}

// ================= standalone conv (agg2 -> a2hi/lo, normalized) =================
__global__ void conv_node(const float* __restrict__ src,
                          __nv_bfloat16* __restrict__ hi,
                          __nv_bfloat16* __restrict__ lo, int useNorm) {
    conv_node_body(blockIdx.x * 256 + threadIdx.x, src, hi, lo, useNorm != 0);
}

// ================= mma helpers =================
__device__ __forceinline__ uint32_t smem_u32(const void* p) {
    return (uint32_t)__cvta_generic_to_shared(p);
}
__device__ __forceinline__ void ldsm4(uint32_t* r, uint32_t addr) {
    asm volatile("ldmatrix.sync.aligned.m8n8.x4.shared.b16 {%0,%1,%2,%3}, [%4];"
                 : "=r"(r[0]), "=r"(r[1]), "=r"(r[2]), "=r"(r[3]) : "r"(addr));
}
__device__ __forceinline__ void ldsm2(uint32_t* r, uint32_t addr) {
    asm volatile("ldmatrix.sync.aligned.m8n8.x2.shared.b16 {%0,%1}, [%2];"
                 : "=r"(r[0]), "=r"(r[1]) : "r"(addr));
}
__device__ __forceinline__ void mma_bf16(float* c, const uint32_t* a, const uint32_t* b) {
    asm volatile(
        "mma.sync.aligned.m16n8k16.row.col.f32.bf16.bf16.f32 "
        "{%0,%1,%2,%3}, {%4,%5,%6,%7}, {%8,%9}, {%0,%1,%2,%3};"
        : "+f"(c[0]), "+f"(c[1]), "+f"(c[2]), "+f"(c[3])
        : "r"(a[0]), "r"(a[1]), "r"(a[2]), "r"(a[3]), "r"(b[0]), "r"(b[1]));
}
__device__ __forceinline__ void cpa16(uint32_t dsts, const void* src, bool valid) {
    int sz = valid ? 16 : 0;
    asm volatile("cp.async.cg.shared.global [%0], [%1], 16, %2;"
                 :: "r"(dsts), "l"(src), "r"(sz));
}
#define CP_COMMIT() asm volatile("cp.async.commit_group;" ::: "memory")
#define CP_WAIT1()  asm volatile("cp.async.wait_group 1;" ::: "memory")
#define CP_WAIT0()  asm volatile("cp.async.wait_group 0;" ::: "memory")

// ================= occupancy-2 3-term MMA GEMM (R14-16-proven core;
// WRITE_H1 branch removed — h1 bf16 conversion moved to edge2 tail) =================
template <int NPASS, bool HAS_AGG>
__global__ void __launch_bounds__(256, 2) mma_gemm(
    const __nv_bfloat16* __restrict__ A0h, const __nv_bfloat16* __restrict__ A0l,
    const __nv_bfloat16* __restrict__ B0h, const __nv_bfloat16* __restrict__ B0l,
    const __nv_bfloat16* __restrict__ A1h, const __nv_bfloat16* __restrict__ A1l,
    const __nv_bfloat16* __restrict__ B1h, const __nv_bfloat16* __restrict__ B1l,
    const __nv_bfloat16* __restrict__ A2h, const __nv_bfloat16* __restrict__ A2l,
    const __nv_bfloat16* __restrict__ B2h, const __nv_bfloat16* __restrict__ B2l,
    const float* __restrict__ bias, float* __restrict__ outf) {
    extern __shared__ __align__(128) char smem[];
    uint32_t sb = smem_u32(smem);

    int tid = threadIdx.x;
    int lane = tid & 31;
    int wid = tid >> 5;
    int wm = wid & 3;
    int wn = wid >> 2;
    int row0 = blockIdx.x * BM;

    float acc[13][4];
#pragma unroll
    for (int nt = 0; nt < 13; nt++)
#pragma unroll
        for (int q = 0; q < 4; q++) acc[nt][q] = 0.0f;

    const __nv_bfloat16* Ahp[3] = {A0h, A1h, A2h};
    const __nv_bfloat16* Alp[3] = {A0l, A1l, A2l};
    const __nv_bfloat16* Bhp[3] = {B0h, B1h, B2h};
    const __nv_bfloat16* Blp[3] = {B0l, B1l, B2l};

    const int total = NPASS * 7;

    auto load_chunk = [&](int t, int stage) {
        int p = t / 7, c = t - p * 7;
        int kb = c * 32;
        int sh = (c == 6) ? 1 : 2;
        int msk = (1 << sh) - 1;
        uint32_t base = sb + stage * STAGE_BYTES;
        const __nv_bfloat16* Ah = Ahp[p];
        const __nv_bfloat16* Al = Alp[p];
        const __nv_bfloat16* Bh = Bhp[p];
        const __nv_bfloat16* Bl = Blp[p];
        int nA = 64 << sh;
        for (int i = tid; i < nA; i += 256) {
            int r = i >> sh, u = i & msk;
            int gr = row0 + r;
            bool v = gr < NN;
            long off = (long)gr * KP + kb + u * 8;
            cpa16(base + SO_AHI + r * 80 + u * 16, Ah + off, v);
            cpa16(base + SO_ALO + r * 80 + u * 16, Al + off, v);
        }
        int nB = 208 << sh;
        for (int i = tid; i < nB; i += 256) {
            int r = i >> sh, u = i & msk;
            long off = (long)r * KP + kb + u * 8;
            cpa16(base + SO_BHI + r * 80 + u * 16, Bh + off, true);
            cpa16(base + SO_BLO + r * 80 + u * 16, Bl + off, true);
        }
        CP_COMMIT();
    };

    uint32_t a_off = (uint32_t)((wm * 16 + (lane & 15)) * 80 + (((lane >> 4) << 3) << 1));
    uint32_t b_off = (uint32_t)((wn * 104 + (lane & 7) + ((lane >> 4) << 3)) * 80 +
                                ((((lane >> 3) & 1) << 3) << 1));
    uint32_t b2_off = (uint32_t)((wn * 104 + 96 + (lane & 7)) * 80 +
                                 ((((lane >> 3) & 1) << 3) << 1));

    load_chunk(0, 0);

#pragma unroll 1
    for (int t = 0; t < total; t++) {
        if (t + 1 < total) {
            load_chunk(t + 1, (t + 1) & 1);
            CP_WAIT1();
        } else {
            CP_WAIT0();
        }
        __syncthreads();

        int c = t - (t / 7) * 7;
        int nk16 = (c == 6) ? 1 : 2;
        uint32_t base = sb + (t & 1) * STAGE_BYTES;
#pragma unroll
        for (int k16 = 0; k16 < 2; k16++) {
            if (k16 >= nk16) break;
            uint32_t kofs = (uint32_t)(k16 << 5);
            uint32_t ah[4], al[4];
            ldsm4(ah, base + SO_AHI + a_off + kofs);
            ldsm4(al, base + SO_ALO + a_off + kofs);
#pragma unroll
            for (int bt = 0; bt < 6; bt++) {
                uint32_t bh[4], bl[4];
                ldsm4(bh, base + SO_BHI + b_off + bt * (16 * 80) + kofs);
                ldsm4(bl, base + SO_BLO + b_off + bt * (16 * 80) + kofs);
                mma_bf16(acc[2 * bt],     ah, bh);
                mma_bf16(acc[2 * bt + 1], ah, bh + 2);
                mma_bf16(acc[2 * bt],     ah, bl);
                mma_bf16(acc[2 * bt + 1], ah, bl + 2);
                mma_bf16(acc[2 * bt],     al, bh);
                mma_bf16(acc[2 * bt + 1], al, bh + 2);
            }
            {
                uint32_t bh[2], bl[2];
                ldsm2(bh, base + SO_BHI + b2_off + kofs);
                ldsm2(bl, base + SO_BLO + b2_off + kofs);
                mma_bf16(acc[12], ah, bh);
                mma_bf16(acc[12], ah, bl);
                mma_bf16(acc[12], al, bh);
            }
        }
        __syncthreads();
    }

    // ---- epilogue ----
    int r0 = row0 + wm * 16 + (lane >> 2);
#pragma unroll
    for (int half = 0; half < 2; half++) {
        int gr = r0 + half * 8;
        if (gr >= NN) continue;
        float nv = HAS_AGG ? g_norm[gr] : 0.0f;
#pragma unroll
        for (int nt = 0; nt < 13; nt++) {
            int col = wn * 104 + nt * 8 + ((lane & 3) << 1);
            if (col >= DD) continue;
            float v0 = acc[nt][half * 2 + 0];
            float v1 = acc[nt][half * 2 + 1];
            if (HAS_AGG) {
                float2 ag = *(const float2*)(g_agg + (long)gr * DD + col);
                v0 += ag.x * nv;
                v1 += ag.y * nv;
            }
            float2 bb = *(const float2*)(bias + col);
            v0 = tanhf(v0 + bb.x);
            v1 = tanhf(v1 + bb.y);
            *(float2*)(outf + (long)gr * DD + col) = make_float2(v0, v1);
        }
    }
}

// ================= launch =================
extern "C" void kernel_launch(void* const* d_in, const int* in_sizes, int n_in,
                              void* d_out, int out_size) {
    const float* node_feat = (const float*)d_in[0];
    const float* dyn       = (const float*)d_in[1];
    const int*   src       = (const int*)d_in[2];
    const int*   dst       = (const int*)d_in[3];
    const int*   et        = (const int*)d_in[4];
    const float* w1        = (const float*)d_in[5];
    const float* lw1       = (const float*)d_in[6];
    const float* b1        = (const float*)d_in[7];
    const float* w2        = (const float*)d_in[8];
    const float* lw2       = (const float*)d_in[9];
    const float* b2        = (const float*)d_in[10];
    const float* Wih       = (const float*)d_in[11];
    const float* Whh       = (const float*)d_in[12];
    const float* bih       = (const float*)d_in[13];
    const float* bhh       = (const float*)d_in[14];
    float* out = (float*)d_out;

    void *agg_p, *agg2_p, *norm_p, *h1_p, *bfin_p;
    void *xhi, *xlo, *h1hi, *h1lo, *a2hi, *a2lo, *h0hi, *h0lo;
    void *w1hi, *w1lo, *wihhi, *wihlo, *whhhi, *whhlo, *mthi, *mtlo;
    cudaGetSymbolAddress(&agg_p, g_agg);
    cudaGetSymbolAddress(&agg2_p, g_agg2);
    cudaGetSymbolAddress(&norm_p, g_norm);
    cudaGetSymbolAddress(&h1_p, g_h1);
    cudaGetSymbolAddress(&bfin_p, g_bfin);
    cudaGetSymbolAddress(&xhi, g_xhi);     cudaGetSymbolAddress(&xlo, g_xlo);
    cudaGetSymbolAddress(&h1hi, g_h1hi);   cudaGetSymbolAddress(&h1lo, g_h1lo);
    cudaGetSymbolAddress(&a2hi, g_a2hi);   cudaGetSymbolAddress(&a2lo, g_a2lo);
    cudaGetSymbolAddress(&h0hi, g_h0hi);   cudaGetSymbolAddress(&h0lo, g_h0lo);
    cudaGetSymbolAddress(&w1hi, g_w1hi);   cudaGetSymbolAddress(&w1lo, g_w1lo);
    cudaGetSymbolAddress(&wihhi, g_wihhi); cudaGetSymbolAddress(&wihlo, g_wihlo);
    cudaGetSymbolAddress(&whhhi, g_whhhi); cudaGetSymbolAddress(&whhlo, g_whhlo);
    cudaGetSymbolAddress(&mthi, g_mthi);   cudaGetSymbolAddress(&mtlo, g_mtlo);

    cudaFuncSetAttribute(mma_gemm<1, true>,
                         cudaFuncAttributeMaxDynamicSharedMemorySize, SM_TOT);
    cudaFuncSetAttribute(mma_gemm<3, false>,
                         cudaFuncAttributeMaxDynamicSharedMemorySize, SM_TOT);

    // all memsets upfront
    cudaMemsetAsync(agg_p, 0, sizeof(float) * NN * DD);
    cudaMemsetAsync(agg2_p, 0, sizeof(float) * NN * DD);
    cudaMemsetAsync(norm_p, 0, sizeof(float) * NN);

    // fused prep: deg + pack + 3x conv_weight + bmt + bias + 2x conv_node
    mega_prep<<<MEGA_GRID, 256>>>(node_feat, dyn, src, dst, et,
                                  lw1, Wih, Whh, lw2, b2, bih, bhh);

    // layer 1: edge scatter + norm-invert tail
    edge1_kernel<<<EB + NRMB, 256>>>(node_feat, w1);
    // h1 = tanh(x@lw1 + agg1/deg + b1)  (fp32 only; bf16 conv deferred to edge2)
    mma_gemm<1, true><<<NTILES, 256, SM_TOT>>>(
        (const __nv_bfloat16*)xhi, (const __nv_bfloat16*)xlo,
        (const __nv_bfloat16*)w1hi, (const __nv_bfloat16*)w1lo,
        nullptr, nullptr, nullptr, nullptr,
        nullptr, nullptr, nullptr, nullptr,
        b1, (float*)h1_p);

    // layer 2: edge scatter into g_agg2 + h1->bf16 conversion tail
    edge2_kernel<<<EB + CNB, 256>>>((const float*)h1_p, w2);
    conv_node<<<CNB, 256>>>((const float*)agg2_p, (__nv_bfloat16*)a2hi,
                            (__nv_bfloat16*)a2lo, 1);

    // fused final: out = tanh( agg2n@Wih^T + h1@(lw2@Wih^T) + h0@Whh^T + bfin )
    mma_gemm<3, false><<<NTILES, 256, SM_TOT>>>(
        (const __nv_bfloat16*)a2hi, (const __nv_bfloat16*)a2lo,
        (const __nv_bfloat16*)wihhi, (const __nv_bfloat16*)wihlo,
        (const __nv_bfloat16*)h1hi, (const __nv_bfloat16*)h1lo,
        (const __nv_bfloat16*)mthi, (const __nv_bfloat16*)mtlo,
        (const __nv_bfloat16*)h0hi, (const __nv_bfloat16*)h0lo,
        (const __nv_bfloat16*)whhhi, (const __nv_bfloat16*)whhlo,
        (const float*)bfin_p, out);
}